// round 11
// baseline (speedup 1.0000x reference)
#include <cuda_runtime.h>
#include <cuda_fp16.h>
#include <cstdint>
#include <math.h>

#define B_     32
#define CIN    128
#define H_     112
#define W_     112
#define COUT   256
#define E_     4
#define HOUT   56
#define WOUT   56
#define RTAPS  (CIN*9)          // 1152

// ---------------- scratch (device globals) ----------------
__device__ __align__(256) float  g_rw[B_ * E_];
__device__ __align__(256) float  g_rowsum[(size_t)B_ * H_ * CIN];
__device__ __align__(256) __half g_xh[(size_t)B_ * H_ * W_ * CIN];   // NHWC fp16
__device__ __align__(256) __half g_wh[(size_t)B_ * COUT * RTAPS];    // [b][oc][t*128+ic]

// ---------------- PTX helpers ----------------
__device__ __forceinline__ uint32_t smem_u32(const void* p) {
    uint32_t a;
    asm("{ .reg .u64 t; cvta.to.shared.u64 t, %1; cvt.u32.u64 %0, t; }" : "=r"(a) : "l"(p));
    return a;
}
#define CPASYNC(dst, src, sz) \
    asm volatile("cp.async.cg.shared.global [%0], [%1], 16, %2;" \
                 :: "r"(dst), "l"(src), "r"(sz) : "memory")
#define CPCOMMIT() asm volatile("cp.async.commit_group;" ::: "memory")
#define CPWAIT1()  asm volatile("cp.async.wait_group 1;" ::: "memory")
#define CPWAIT0()  asm volatile("cp.async.wait_group 0;" ::: "memory")

#define LDSM_X4(r0, r1, r2, r3, addr) \
    asm volatile("ldmatrix.sync.aligned.m8n8.x4.shared.b16 {%0,%1,%2,%3}, [%4];" \
                 : "=r"(r0), "=r"(r1), "=r"(r2), "=r"(r3) : "r"(addr))
#define LDSM_X2(r0, r1, addr) \
    asm volatile("ldmatrix.sync.aligned.m8n8.x2.shared.b16 {%0,%1}, [%2];" \
                 : "=r"(r0), "=r"(r1) : "r"(addr))

// fp16-accumulating HMMA: D(f16x2 x2) = A*B + C(f16x2 x2)
#define MMA16816_F16(d, a, b0, b1) \
    asm volatile("mma.sync.aligned.m16n8k16.row.col.f16.f16.f16.f16 " \
                 "{%0,%1}, {%2,%3,%4,%5}, {%6,%7}, {%0,%1};" \
                 : "+r"((d)[0]), "+r"((d)[1]) \
                 : "r"((a)[0]), "r"((a)[1]), "r"((a)[2]), "r"((a)[3]), \
                   "r"(b0), "r"(b1))

__device__ __forceinline__ uint32_t sw128(uint32_t off) {
    return off ^ ((off >> 3) & 0x70);
}

// ---------------------------------------------------------------------------
// 1) NCHW fp32 -> NHWC fp16 transpose + per-row pooling sums.
// ---------------------------------------------------------------------------
#define TS 113
#define SPLIT_SMEM (CIN * TS * 4)   // 57856 bytes

__global__ __launch_bounds__(512) void split_x_kernel(const float* __restrict__ x,
                                                      __half* __restrict__ xh,
                                                      float* __restrict__ rowsum) {
    extern __shared__ float tile[];   // [128][113]
    int tid = threadIdx.x;
    int bh = blockIdx.x;
    int b = bh / H_, ih = bh % H_;

    const float* src = x + ((size_t)b * CIN) * (H_ * W_) + (size_t)ih * W_;
    #pragma unroll
    for (int rep = 0; rep < 7; rep++) {
        int i = tid + rep * 512;
        int ic = i / 28, q = i - ic * 28;
        float4 v = *(const float4*)(src + (size_t)ic * (H_ * W_) + q * 4);
        float* tp = &tile[ic * TS + q * 4];
        tp[0] = v.x; tp[1] = v.y; tp[2] = v.z; tp[3] = v.w;
    }
    __syncthreads();

    if (tid < CIN) {
        const float* tp = &tile[tid * TS];
        float s = 0.f;
        #pragma unroll 8
        for (int iw = 0; iw < W_; iw++) s += tp[iw];
        rowsum[((size_t)b * H_ + ih) * CIN + tid] = s;
    }

    size_t obase = (((size_t)b * H_ + ih) * W_) * CIN;
    #pragma unroll
    for (int rep = 0; rep < 14; rep++) {
        int i = tid + rep * 512;
        int iw = i >> 6, icp = i & 63;
        float v0 = tile[(2 * icp) * TS + iw];
        float v1 = tile[(2 * icp + 1) * TS + iw];
        *(__half2*)(xh + obase + (size_t)iw * CIN + icp * 2) =
            __floats2half2_rn(v0, v1);
    }
}

// ---------------------------------------------------------------------------
// 1b) Fused pool-reduce + routing: one block per b.
// ---------------------------------------------------------------------------
__global__ __launch_bounds__(128) void pool_route_kernel(const float* __restrict__ rowsum,
                                                         const float* __restrict__ rw_w,
                                                         const float* __restrict__ rw_b,
                                                         float* __restrict__ rw) {
    __shared__ float pooled[CIN];
    int b = blockIdx.x, ic = threadIdx.x;
    float s = 0.f;
    const float* rs = rowsum + (size_t)b * H_ * CIN + ic;
    #pragma unroll 4
    for (int ih = 0; ih < H_; ih++) s += rs[(size_t)ih * CIN];
    pooled[ic] = s * (1.0f / (H_ * W_));
    __syncthreads();

    int wid = ic >> 5, lane = ic & 31;
    float z = 0.f;
    const float* ww = rw_w + wid * CIN;
    #pragma unroll
    for (int k = lane; k < CIN; k += 32) z += pooled[k] * ww[k];
    #pragma unroll
    for (int off = 16; off > 0; off >>= 1)
        z += __shfl_xor_sync(0xFFFFFFFFu, z, off);
    if (lane == 0)
        rw[b * E_ + wid] = 1.0f / (1.0f + expf(-(z + rw_b[wid])));
}

// ---------------------------------------------------------------------------
// 2) Mix expert weights -> per-sample fp16. Block = (oc, b-group of 8).
// ---------------------------------------------------------------------------
#define BGRP 8
__global__ __launch_bounds__(128) void combine_kernel(const float* __restrict__ ew,
                                                      const float* __restrict__ rw,
                                                      __half* __restrict__ wh) {
    __shared__ float srw[B_ * E_];
    int oc = blockIdx.x;
    int bg = blockIdx.y * BGRP;
    int ic = threadIdx.x;
    srw[ic] = rw[ic];
    __syncthreads();

    float w[E_][9];
    #pragma unroll
    for (int e = 0; e < E_; e++) {
        const float* p = ew + (((size_t)e * COUT + oc) * CIN + ic) * 9;
        #pragma unroll
        for (int t = 0; t < 9; t++) w[e][t] = p[t];
    }

    #pragma unroll 1
    for (int bi = 0; bi < BGRP; bi++) {
        int b = bg + bi;
        float r0 = srw[b * 4 + 0], r1 = srw[b * 4 + 1];
        float r2 = srw[b * 4 + 2], r3 = srw[b * 4 + 3];
        size_t ob = ((size_t)b * COUT + oc) * RTAPS + ic;
        #pragma unroll
        for (int t = 0; t < 9; t++) {
            float v = w[0][t] * r0 + w[1][t] * r1 + w[2][t] * r2 + w[3][t] * r3;
            wh[ob + (size_t)t * 128] = __float2half_rn(v);
        }
    }
}

// ---------------------------------------------------------------------------
// 3) Implicit-GEMM conv via fp16-accum mma.sync with fp32 spill per K=128.
//    Block: (b, 128 oc, 2 out rows, N=112). 256 threads, 8 warps, 3-stage
//    cp.async pipeline (structure identical to the proven R5/R10 version).
// ---------------------------------------------------------------------------
#define A_BYTES     16384
#define BB_BYTES    14336
#define STAGE_BYTES (A_BYTES + BB_BYTES)  // 30720
#define NSTAGE      3
#define SM_TOTAL    (NSTAGE * STAGE_BYTES)  // 92160

__device__ __forceinline__ void load_chunk(int c, uint32_t smb, int stage,
                                           const __half* __restrict__ wbase,
                                           const __half* __restrict__ xb,
                                           int oh0, int tid) {
    int t = c >> 1, h = c & 1;
    int dy = t / 3, dx = t - 3 * dy;
    uint32_t sa = smb + stage * STAGE_BYTES;
    uint32_t sb = sa + A_BYTES;

    const __half* wp = wbase + t * 128 + h * 64;
    #pragma unroll
    for (int rep = 0; rep < 4; rep++) {
        int idx = tid + rep * 256;
        int row = idx >> 3, seg = idx & 7;
        const char* src = (const char*)(wp + (size_t)row * RTAPS) + seg * 16;
        CPASYNC(sa + sw128((uint32_t)(idx * 16)), src, 16);
    }
    #pragma unroll
    for (int rep = 0; rep < 4; rep++) {
        int idx = tid + rep * 256;
        if (idx < 896) {
            int n = idx >> 3, seg = idx & 7;
            int p = (n >= 56) ? 1 : 0;
            int ow = n - 56 * p;
            int ih = 2 * (oh0 + p) - 1 + dy;
            int iw = 2 * ow - 1 + dx;
            bool ok = ((unsigned)ih < (unsigned)H_) && ((unsigned)iw < (unsigned)W_);
            const char* src = ok
                ? (const char*)(xb + ((size_t)ih * W_ + iw) * CIN + h * 64) + seg * 16
                : (const char*)xb;
            CPASYNC(sb + sw128((uint32_t)(idx * 16)), src, ok ? 16u : 0u);
        }
    }
}

__global__ __launch_bounds__(256, 2) void conv_mma_kernel(const __half* __restrict__ xh,
                                                          const __half* __restrict__ wgt,
                                                          float* __restrict__ out) {
    extern __shared__ char sm[];
    uint32_t smb = smem_u32(sm);
    int tid = threadIdx.x, lane = tid & 31, wid = tid >> 5;
    int wm = wid & 3, wn = wid >> 2;
    int oh0 = blockIdx.x * 2;
    int ocb = blockIdx.y, b = blockIdx.z;

    const __half* wbase = wgt + ((size_t)b * COUT + ocb * 128) * RTAPS;
    const __half* xb = xh + (size_t)b * (H_ * W_) * CIN;

    float acc[2][7][4];        // fp32 master accumulators
    uint32_t a16[2][7][2];     // fp16 group accumulators (packed half2 x2)
    #pragma unroll
    for (int mt = 0; mt < 2; mt++)
        #pragma unroll
        for (int nt = 0; nt < 7; nt++)
            #pragma unroll
            for (int q = 0; q < 4; q++) acc[mt][nt][q] = 0.f;

    load_chunk(0, smb, 0, wbase, xb, oh0, tid);
    CPCOMMIT();
    load_chunk(1, smb, 1, wbase, xb, oh0, tid);
    CPCOMMIT();

    int st = 0, st2 = 2;
    for (int c = 0; c < 18; c++) {
        if (c < 17) { CPWAIT1(); } else { CPWAIT0(); }
        __syncthreads();

        if (c + 2 < 18) {
            load_chunk(c + 2, smb, st2, wbase, xb, oh0, tid);
            CPCOMMIT();
        }

        // zero fp16 group accumulators at the start of each K=128 group
        if ((c & 1) == 0) {
            #pragma unroll
            for (int mt = 0; mt < 2; mt++)
                #pragma unroll
                for (int nt = 0; nt < 7; nt++) {
                    a16[mt][nt][0] = 0u;
                    a16[mt][nt][1] = 0u;
                }
        }

        uint32_t sa = smb + st * STAGE_BYTES;
        uint32_t sb = sa + A_BYTES;

        #pragma unroll
        for (int ks = 0; ks < 4; ks++) {
            int k0 = ks * 16;
            uint32_t afr[2][4];
            #pragma unroll
            for (int mt = 0; mt < 2; mt++) {
                int row = wm * 32 + mt * 16 + (lane & 15);
                int kk = k0 + ((lane >> 4) << 3);
                LDSM_X4(afr[mt][0], afr[mt][1], afr[mt][2], afr[mt][3],
                        sa + sw128((uint32_t)(row * 128 + kk * 2)));
            }
            uint32_t bfr[7][2];
            #pragma unroll
            for (int j = 0; j < 3; j++) {
                int n = wn * 56 + j * 16 + (lane & 7) + ((lane >> 4) << 3);
                int kk = k0 + (((lane >> 3) & 1) << 3);
                LDSM_X4(bfr[2 * j][0], bfr[2 * j][1], bfr[2 * j + 1][0], bfr[2 * j + 1][1],
                        sb + sw128((uint32_t)(n * 128 + kk * 2)));
            }
            {
                int n = wn * 56 + 48 + (lane & 7);
                int kk = k0 + (((lane >> 3) & 1) << 3);
                LDSM_X2(bfr[6][0], bfr[6][1],
                        sb + sw128((uint32_t)(n * 128 + kk * 2)));
            }
            #pragma unroll
            for (int mt = 0; mt < 2; mt++)
                #pragma unroll
                for (int nt = 0; nt < 7; nt++)
                    MMA16816_F16(a16[mt][nt], afr[mt], bfr[nt][0], bfr[nt][1]);
        }

        // spill fp16 group accumulators into fp32 at the end of each group
        if ((c & 1) == 1) {
            #pragma unroll
            for (int mt = 0; mt < 2; mt++)
                #pragma unroll
                for (int nt = 0; nt < 7; nt++) {
                    float2 f0 = __half22float2(*(__half2*)&a16[mt][nt][0]);
                    float2 f1 = __half22float2(*(__half2*)&a16[mt][nt][1]);
                    acc[mt][nt][0] += f0.x;
                    acc[mt][nt][1] += f0.y;
                    acc[mt][nt][2] += f1.x;
                    acc[mt][nt][3] += f1.y;
                }
        }

        st = (st == NSTAGE - 1) ? 0 : st + 1;
        st2 = (st2 == NSTAGE - 1) ? 0 : st2 + 1;
    }

    // ---- epilogue ----
    int r = lane >> 2;
    int cb = (lane & 3) * 2;
    int oh = oh0 + wn;
    #pragma unroll
    for (int mt = 0; mt < 2; mt++) {
        int oc = ocb * 128 + wm * 32 + mt * 16 + r;
        #pragma unroll
        for (int nt = 0; nt < 7; nt++) {
            int ow = nt * 8 + cb;
            float* op = out + (((size_t)b * COUT + oc) * HOUT + oh) * WOUT + ow;
            *(float2*)op = make_float2(acc[mt][nt][0], acc[mt][nt][1]);
            *(float2*)(op + (size_t)8 * HOUT * WOUT) =
                make_float2(acc[mt][nt][2], acc[mt][nt][3]);   // oc + 8
        }
    }
}

// ---------------------------------------------------------------------------
extern "C" void kernel_launch(void* const* d_in, const int* in_sizes, int n_in,
                              void* d_out, int out_size) {
    const float* x    = (const float*)d_in[0];
    const float* rw_w = (const float*)d_in[1];
    const float* rw_b = (const float*)d_in[2];
    const float* ew   = (const float*)d_in[3];
    float* out = (float*)d_out;

    float *rw, *rowsum;
    __half *xh, *wh;
    cudaGetSymbolAddress((void**)&rw, g_rw);
    cudaGetSymbolAddress((void**)&rowsum, g_rowsum);
    cudaGetSymbolAddress((void**)&xh, g_xh);
    cudaGetSymbolAddress((void**)&wh, g_wh);

    cudaFuncSetAttribute(split_x_kernel,
                         cudaFuncAttributeMaxDynamicSharedMemorySize, SPLIT_SMEM);
    split_x_kernel<<<B_ * H_, 512, SPLIT_SMEM>>>(x, xh, rowsum);
    pool_route_kernel<<<B_, 128>>>(rowsum, rw_w, rw_b, rw);
    combine_kernel<<<dim3(COUT, B_ / BGRP), CIN>>>(ew, rw, wh);

    cudaFuncSetAttribute(conv_mma_kernel,
                         cudaFuncAttributeMaxDynamicSharedMemorySize, SM_TOTAL);
    conv_mma_kernel<<<dim3(HOUT / 2, 2, B_), 256, SM_TOTAL>>>(xh, wh, out);
}

// round 13
// speedup vs baseline: 1.1200x; 1.1200x over previous
#include <cuda_runtime.h>
#include <cuda_fp16.h>
#include <cstdint>
#include <math.h>

#define B_     32
#define CIN    128
#define H_     112
#define W_     112
#define COUT   256
#define E_     4
#define HOUT   56
#define WOUT   56
#define RTAPS  (CIN*9)          // 1152

// ---------------- scratch (device globals) ----------------
__device__ __align__(256) float  g_rw[B_ * E_];
__device__ __align__(256) float  g_rowsum[(size_t)B_ * H_ * CIN];
__device__ __align__(256) __half g_xh[(size_t)B_ * H_ * W_ * CIN];   // NHWC fp16
__device__ __align__(256) __half g_wh[(size_t)B_ * COUT * RTAPS];    // [b][oc][t*128+ic]

// ---------------- PTX helpers ----------------
__device__ __forceinline__ uint32_t smem_u32(const void* p) {
    uint32_t a;
    asm("{ .reg .u64 t; cvta.to.shared.u64 t, %1; cvt.u32.u64 %0, t; }" : "=r"(a) : "l"(p));
    return a;
}
#define CPASYNC(dst, src, sz) \
    asm volatile("cp.async.cg.shared.global [%0], [%1], 16, %2;" \
                 :: "r"(dst), "l"(src), "r"(sz) : "memory")
#define CPCOMMIT() asm volatile("cp.async.commit_group;" ::: "memory")
#define CPWAIT1()  asm volatile("cp.async.wait_group 1;" ::: "memory")
#define CPWAIT0()  asm volatile("cp.async.wait_group 0;" ::: "memory")

#define LDSM_X4(r0, r1, r2, r3, addr) \
    asm volatile("ldmatrix.sync.aligned.m8n8.x4.shared.b16 {%0,%1,%2,%3}, [%4];" \
                 : "=r"(r0), "=r"(r1), "=r"(r2), "=r"(r3) : "r"(addr))
#define LDSM_X2(r0, r1, addr) \
    asm volatile("ldmatrix.sync.aligned.m8n8.x2.shared.b16 {%0,%1}, [%2];" \
                 : "=r"(r0), "=r"(r1) : "r"(addr))

#define MMA16816(d, a, b0, b1) \
    asm volatile("mma.sync.aligned.m16n8k16.row.col.f32.f16.f16.f32 " \
                 "{%0,%1,%2,%3}, {%4,%5,%6,%7}, {%8,%9}, {%0,%1,%2,%3};" \
                 : "+f"((d)[0]), "+f"((d)[1]), "+f"((d)[2]), "+f"((d)[3]) \
                 : "r"((a)[0]), "r"((a)[1]), "r"((a)[2]), "r"((a)[3]), \
                   "r"(b0), "r"(b1))

__device__ __forceinline__ uint32_t sw128(uint32_t off) {
    return off ^ ((off >> 3) & 0x70);
}

// ---------------------------------------------------------------------------
// 1) NCHW fp32 -> NHWC fp16 transpose + per-row pooling sums.
//    (Byte-identical to the proven R10 version: float4 reads, half2 writes.)
// ---------------------------------------------------------------------------
#define TS 113
#define SPLIT_SMEM (CIN * TS * 4)   // 57856 bytes

__global__ __launch_bounds__(512) void split_x_kernel(const float* __restrict__ x,
                                                      __half* __restrict__ xh,
                                                      float* __restrict__ rowsum) {
    extern __shared__ float tile[];   // [128][113]
    int tid = threadIdx.x;
    int bh = blockIdx.x;
    int b = bh / H_, ih = bh % H_;

    const float* src = x + ((size_t)b * CIN) * (H_ * W_) + (size_t)ih * W_;
    #pragma unroll
    for (int rep = 0; rep < 7; rep++) {
        int i = tid + rep * 512;
        int ic = i / 28, q = i - ic * 28;
        float4 v = *(const float4*)(src + (size_t)ic * (H_ * W_) + q * 4);
        float* tp = &tile[ic * TS + q * 4];
        tp[0] = v.x; tp[1] = v.y; tp[2] = v.z; tp[3] = v.w;
    }
    __syncthreads();

    if (tid < CIN) {
        const float* tp = &tile[tid * TS];
        float s = 0.f;
        #pragma unroll 8
        for (int iw = 0; iw < W_; iw++) s += tp[iw];
        rowsum[((size_t)b * H_ + ih) * CIN + tid] = s;
    }

    size_t obase = (((size_t)b * H_ + ih) * W_) * CIN;
    #pragma unroll
    for (int rep = 0; rep < 14; rep++) {
        int i = tid + rep * 512;
        int iw = i >> 6, icp = i & 63;
        float v0 = tile[(2 * icp) * TS + iw];
        float v1 = tile[(2 * icp + 1) * TS + iw];
        *(__half2*)(xh + obase + (size_t)iw * CIN + icp * 2) =
            __floats2half2_rn(v0, v1);
    }
}

// ---------------------------------------------------------------------------
// 1b) Fused pool-reduce + routing: one block per b.
// ---------------------------------------------------------------------------
__global__ __launch_bounds__(128) void pool_route_kernel(const float* __restrict__ rowsum,
                                                         const float* __restrict__ rw_w,
                                                         const float* __restrict__ rw_b,
                                                         float* __restrict__ rw) {
    __shared__ float pooled[CIN];
    int b = blockIdx.x, ic = threadIdx.x;
    float s = 0.f;
    const float* rs = rowsum + (size_t)b * H_ * CIN + ic;
    #pragma unroll 4
    for (int ih = 0; ih < H_; ih++) s += rs[(size_t)ih * CIN];
    pooled[ic] = s * (1.0f / (H_ * W_));
    __syncthreads();

    int wid = ic >> 5, lane = ic & 31;
    float z = 0.f;
    const float* ww = rw_w + wid * CIN;
    #pragma unroll
    for (int k = lane; k < CIN; k += 32) z += pooled[k] * ww[k];
    #pragma unroll
    for (int off = 16; off > 0; off >>= 1)
        z += __shfl_xor_sync(0xFFFFFFFFu, z, off);
    if (lane == 0)
        rw[b * E_ + wid] = 1.0f / (1.0f + expf(-(z + rw_b[wid])));
}

// ---------------------------------------------------------------------------
// 2) Mix expert weights -> per-sample fp16, half2 coalesced stores.
//    Block = 128 threads = 2 oc x 64 ic-pairs; grid (COUT/2, B/BGRP).
// ---------------------------------------------------------------------------
#define BGRP 8
__global__ __launch_bounds__(128) void combine_kernel(const float* __restrict__ ew,
                                                      const float* __restrict__ rw,
                                                      __half* __restrict__ wh) {
    __shared__ float srw[B_ * E_];
    int tid = threadIdx.x;
    int oc = blockIdx.x * 2 + (tid >> 6);
    int icp = tid & 63;          // ic pair index; ic = 2*icp, 2*icp+1
    int bg = blockIdx.y * BGRP;
    srw[tid] = rw[tid];
    __syncthreads();

    float w[E_][2][9];
    #pragma unroll
    for (int e = 0; e < E_; e++) {
        const float* p = ew + (((size_t)e * COUT + oc) * CIN + 2 * icp) * 9;
        #pragma unroll
        for (int t = 0; t < 9; t++) { w[e][0][t] = p[t]; w[e][1][t] = p[9 + t]; }
    }

    #pragma unroll 1
    for (int bi = 0; bi < BGRP; bi++) {
        int b = bg + bi;
        float r0 = srw[b * 4 + 0], r1 = srw[b * 4 + 1];
        float r2 = srw[b * 4 + 2], r3 = srw[b * 4 + 3];
        __half* op = wh + ((size_t)b * COUT + oc) * RTAPS + 2 * icp;
        #pragma unroll
        for (int t = 0; t < 9; t++) {
            float v0 = w[0][0][t] * r0 + w[1][0][t] * r1 + w[2][0][t] * r2 + w[3][0][t] * r3;
            float v1 = w[0][1][t] * r0 + w[1][1][t] * r1 + w[2][1][t] * r2 + w[3][1][t] * r3;
            *(__half2*)(op + (size_t)t * 128) = __floats2half2_rn(v0, v1);
        }
    }
}

// ---------------------------------------------------------------------------
// 3) Implicit-GEMM conv via mma.sync (fp32 accum). Block: (b, 128 oc, 2 out
//    rows, N=112). 256 threads, 8 warps, 3-stage cp.async, 1 sync/chunk.
//    (Byte-identical to the proven 147.6us R10 version.)
// ---------------------------------------------------------------------------
#define A_BYTES     16384
#define BB_BYTES    14336
#define STAGE_BYTES (A_BYTES + BB_BYTES)  // 30720
#define NSTAGE      3
#define SM_TOTAL    (NSTAGE * STAGE_BYTES)  // 92160

__device__ __forceinline__ void load_chunk(int c, uint32_t smb, int stage,
                                           const __half* __restrict__ wbase,
                                           const __half* __restrict__ xb,
                                           int oh0, int tid) {
    int t = c >> 1, h = c & 1;
    int dy = t / 3, dx = t - 3 * dy;
    uint32_t sa = smb + stage * STAGE_BYTES;
    uint32_t sb = sa + A_BYTES;

    const __half* wp = wbase + t * 128 + h * 64;
    #pragma unroll
    for (int rep = 0; rep < 4; rep++) {
        int idx = tid + rep * 256;
        int row = idx >> 3, seg = idx & 7;
        const char* src = (const char*)(wp + (size_t)row * RTAPS) + seg * 16;
        CPASYNC(sa + sw128((uint32_t)(idx * 16)), src, 16);
    }
    #pragma unroll
    for (int rep = 0; rep < 4; rep++) {
        int idx = tid + rep * 256;
        if (idx < 896) {
            int n = idx >> 3, seg = idx & 7;
            int p = (n >= 56) ? 1 : 0;
            int ow = n - 56 * p;
            int ih = 2 * (oh0 + p) - 1 + dy;
            int iw = 2 * ow - 1 + dx;
            bool ok = ((unsigned)ih < (unsigned)H_) && ((unsigned)iw < (unsigned)W_);
            const char* src = ok
                ? (const char*)(xb + ((size_t)ih * W_ + iw) * CIN + h * 64) + seg * 16
                : (const char*)xb;
            CPASYNC(sb + sw128((uint32_t)(idx * 16)), src, ok ? 16u : 0u);
        }
    }
}

__global__ __launch_bounds__(256, 2) void conv_mma_kernel(const __half* __restrict__ xh,
                                                          const __half* __restrict__ wgt,
                                                          float* __restrict__ out) {
    extern __shared__ char sm[];
    uint32_t smb = smem_u32(sm);
    int tid = threadIdx.x, lane = tid & 31, wid = tid >> 5;
    int wm = wid & 3, wn = wid >> 2;
    int oh0 = blockIdx.x * 2;
    int ocb = blockIdx.y, b = blockIdx.z;

    const __half* wbase = wgt + ((size_t)b * COUT + ocb * 128) * RTAPS;
    const __half* xb = xh + (size_t)b * (H_ * W_) * CIN;

    float acc[2][7][4];
    #pragma unroll
    for (int mt = 0; mt < 2; mt++)
        #pragma unroll
        for (int nt = 0; nt < 7; nt++)
            #pragma unroll
            for (int q = 0; q < 4; q++) acc[mt][nt][q] = 0.f;

    load_chunk(0, smb, 0, wbase, xb, oh0, tid);
    CPCOMMIT();
    load_chunk(1, smb, 1, wbase, xb, oh0, tid);
    CPCOMMIT();

    int st = 0, st2 = 2;
    for (int c = 0; c < 18; c++) {
        if (c < 17) { CPWAIT1(); } else { CPWAIT0(); }
        __syncthreads();

        if (c + 2 < 18) {
            load_chunk(c + 2, smb, st2, wbase, xb, oh0, tid);
            CPCOMMIT();
        }

        uint32_t sa = smb + st * STAGE_BYTES;
        uint32_t sb = sa + A_BYTES;

        #pragma unroll
        for (int ks = 0; ks < 4; ks++) {
            int k0 = ks * 16;
            uint32_t afr[2][4];
            #pragma unroll
            for (int mt = 0; mt < 2; mt++) {
                int row = wm * 32 + mt * 16 + (lane & 15);
                int kk = k0 + ((lane >> 4) << 3);
                LDSM_X4(afr[mt][0], afr[mt][1], afr[mt][2], afr[mt][3],
                        sa + sw128((uint32_t)(row * 128 + kk * 2)));
            }
            uint32_t bfr[7][2];
            #pragma unroll
            for (int j = 0; j < 3; j++) {
                int n = wn * 56 + j * 16 + (lane & 7) + ((lane >> 4) << 3);
                int kk = k0 + (((lane >> 3) & 1) << 3);
                LDSM_X4(bfr[2 * j][0], bfr[2 * j][1], bfr[2 * j + 1][0], bfr[2 * j + 1][1],
                        sb + sw128((uint32_t)(n * 128 + kk * 2)));
            }
            {
                int n = wn * 56 + 48 + (lane & 7);
                int kk = k0 + (((lane >> 3) & 1) << 3);
                LDSM_X2(bfr[6][0], bfr[6][1],
                        sb + sw128((uint32_t)(n * 128 + kk * 2)));
            }
            #pragma unroll
            for (int mt = 0; mt < 2; mt++)
                #pragma unroll
                for (int nt = 0; nt < 7; nt++)
                    MMA16816(acc[mt][nt], afr[mt], bfr[nt][0], bfr[nt][1]);
        }

        st = (st == NSTAGE - 1) ? 0 : st + 1;
        st2 = (st2 == NSTAGE - 1) ? 0 : st2 + 1;
    }

    int r = lane >> 2;
    int cb = (lane & 3) * 2;
    int oh = oh0 + wn;
    #pragma unroll
    for (int mt = 0; mt < 2; mt++) {
        int oc = ocb * 128 + wm * 32 + mt * 16 + r;
        #pragma unroll
        for (int nt = 0; nt < 7; nt++) {
            int ow = nt * 8 + cb;
            float* op = out + (((size_t)b * COUT + oc) * HOUT + oh) * WOUT + ow;
            *(float2*)op = make_float2(acc[mt][nt][0], acc[mt][nt][1]);
            *(float2*)(op + (size_t)8 * HOUT * WOUT) =
                make_float2(acc[mt][nt][2], acc[mt][nt][3]);   // oc + 8
        }
    }
}

// ---------------------------------------------------------------------------
extern "C" void kernel_launch(void* const* d_in, const int* in_sizes, int n_in,
                              void* d_out, int out_size) {
    const float* x    = (const float*)d_in[0];
    const float* rw_w = (const float*)d_in[1];
    const float* rw_b = (const float*)d_in[2];
    const float* ew   = (const float*)d_in[3];
    float* out = (float*)d_out;

    float *rw, *rowsum;
    __half *xh, *wh;
    cudaGetSymbolAddress((void**)&rw, g_rw);
    cudaGetSymbolAddress((void**)&rowsum, g_rowsum);
    cudaGetSymbolAddress((void**)&xh, g_xh);
    cudaGetSymbolAddress((void**)&wh, g_wh);

    cudaFuncSetAttribute(split_x_kernel,
                         cudaFuncAttributeMaxDynamicSharedMemorySize, SPLIT_SMEM);
    split_x_kernel<<<B_ * H_, 512, SPLIT_SMEM>>>(x, xh, rowsum);
    pool_route_kernel<<<B_, 128>>>(rowsum, rw_w, rw_b, rw);
    combine_kernel<<<dim3(COUT / 2, B_ / BGRP), 128>>>(ew, rw, wh);

    cudaFuncSetAttribute(conv_mma_kernel,
                         cudaFuncAttributeMaxDynamicSharedMemorySize, SM_TOTAL);
    conv_mma_kernel<<<dim3(HOUT / 2, 2, B_), 256, SM_TOTAL>>>(xh, wh, out);
}

// round 14
// speedup vs baseline: 1.1860x; 1.0590x over previous
#include <cuda_runtime.h>
#include <cuda_fp16.h>
#include <cstdint>
#include <math.h>

#define B_     32
#define HB     16               // half batch
#define CIN    128
#define H_     112
#define W_     112
#define COUT   256
#define E_     4
#define HOUT   56
#define WOUT   56
#define RTAPS  (CIN*9)          // 1152

// ---------------- scratch (device globals) ----------------
__device__ __align__(256) float  g_rw[B_ * E_];
__device__ __align__(256) float  g_rowsum[(size_t)B_ * H_ * CIN];
__device__ __align__(256) __half g_xh[(size_t)B_ * H_ * W_ * CIN];   // NHWC fp16
__device__ __align__(256) __half g_wh[(size_t)B_ * COUT * RTAPS];    // [b][oc][t*128+ic]

// ---------------- PTX helpers ----------------
__device__ __forceinline__ uint32_t smem_u32(const void* p) {
    uint32_t a;
    asm("{ .reg .u64 t; cvta.to.shared.u64 t, %1; cvt.u32.u64 %0, t; }" : "=r"(a) : "l"(p));
    return a;
}
#define CPASYNC(dst, src, sz) \
    asm volatile("cp.async.cg.shared.global [%0], [%1], 16, %2;" \
                 :: "r"(dst), "l"(src), "r"(sz) : "memory")
#define CPCOMMIT() asm volatile("cp.async.commit_group;" ::: "memory")
#define CPWAIT1()  asm volatile("cp.async.wait_group 1;" ::: "memory")
#define CPWAIT0()  asm volatile("cp.async.wait_group 0;" ::: "memory")

#define LDSM_X4(r0, r1, r2, r3, addr) \
    asm volatile("ldmatrix.sync.aligned.m8n8.x4.shared.b16 {%0,%1,%2,%3}, [%4];" \
                 : "=r"(r0), "=r"(r1), "=r"(r2), "=r"(r3) : "r"(addr))
#define LDSM_X2(r0, r1, addr) \
    asm volatile("ldmatrix.sync.aligned.m8n8.x2.shared.b16 {%0,%1}, [%2];" \
                 : "=r"(r0), "=r"(r1) : "r"(addr))

#define MMA16816(d, a, b0, b1) \
    asm volatile("mma.sync.aligned.m16n8k16.row.col.f32.f16.f16.f32 " \
                 "{%0,%1,%2,%3}, {%4,%5,%6,%7}, {%8,%9}, {%0,%1,%2,%3};" \
                 : "+f"((d)[0]), "+f"((d)[1]), "+f"((d)[2]), "+f"((d)[3]) \
                 : "r"((a)[0]), "r"((a)[1]), "r"((a)[2]), "r"((a)[3]), \
                   "r"(b0), "r"(b1))

__device__ __forceinline__ uint32_t sw128(uint32_t off) {
    return off ^ ((off >> 3) & 0x70);
}

// ---------------------------------------------------------------------------
// 1) NCHW fp32 -> NHWC fp16 transpose + per-row pooling sums (half batch).
// ---------------------------------------------------------------------------
#define TS 113
#define SPLIT_SMEM (CIN * TS * 4)   // 57856 bytes

__global__ __launch_bounds__(512) void split_x_kernel(const float* __restrict__ x,
                                                      __half* __restrict__ xh,
                                                      float* __restrict__ rowsum,
                                                      int b0) {
    extern __shared__ float tile[];   // [128][113]
    int tid = threadIdx.x;
    int bh = blockIdx.x;
    int b = b0 + bh / H_, ih = bh % H_;

    const float* src = x + ((size_t)b * CIN) * (H_ * W_) + (size_t)ih * W_;
    #pragma unroll
    for (int rep = 0; rep < 7; rep++) {
        int i = tid + rep * 512;
        int ic = i / 28, q = i - ic * 28;
        float4 v = *(const float4*)(src + (size_t)ic * (H_ * W_) + q * 4);
        float* tp = &tile[ic * TS + q * 4];
        tp[0] = v.x; tp[1] = v.y; tp[2] = v.z; tp[3] = v.w;
    }
    __syncthreads();

    if (tid < CIN) {
        const float* tp = &tile[tid * TS];
        float s = 0.f;
        #pragma unroll 8
        for (int iw = 0; iw < W_; iw++) s += tp[iw];
        rowsum[((size_t)b * H_ + ih) * CIN + tid] = s;
    }

    size_t obase = (((size_t)b * H_ + ih) * W_) * CIN;
    #pragma unroll
    for (int rep = 0; rep < 14; rep++) {
        int i = tid + rep * 512;
        int iw = i >> 6, icp = i & 63;
        float v0 = tile[(2 * icp) * TS + iw];
        float v1 = tile[(2 * icp + 1) * TS + iw];
        *(__half2*)(xh + obase + (size_t)iw * CIN + icp * 2) =
            __floats2half2_rn(v0, v1);
    }
}

// ---------------------------------------------------------------------------
// 1b) Fused pool-reduce + routing: one block per b (half batch).
// ---------------------------------------------------------------------------
__global__ __launch_bounds__(128) void pool_route_kernel(const float* __restrict__ rowsum,
                                                         const float* __restrict__ rw_w,
                                                         const float* __restrict__ rw_b,
                                                         float* __restrict__ rw,
                                                         int b0) {
    __shared__ float pooled[CIN];
    int b = b0 + blockIdx.x, ic = threadIdx.x;
    float s = 0.f;
    const float* rs = rowsum + (size_t)b * H_ * CIN + ic;
    #pragma unroll 4
    for (int ih = 0; ih < H_; ih++) s += rs[(size_t)ih * CIN];
    pooled[ic] = s * (1.0f / (H_ * W_));
    __syncthreads();

    int wid = ic >> 5, lane = ic & 31;
    float z = 0.f;
    const float* ww = rw_w + wid * CIN;
    #pragma unroll
    for (int k = lane; k < CIN; k += 32) z += pooled[k] * ww[k];
    #pragma unroll
    for (int off = 16; off > 0; off >>= 1)
        z += __shfl_xor_sync(0xFFFFFFFFu, z, off);
    if (lane == 0)
        rw[b * E_ + wid] = 1.0f / (1.0f + expf(-(z + rw_b[wid])));
}

// ---------------------------------------------------------------------------
// 2) Mix expert weights -> per-sample fp16, half2 stores (half batch).
//    Block = 128 threads = 2 oc x 64 ic-pairs; grid (COUT/2, HB/BGRP).
// ---------------------------------------------------------------------------
#define BGRP 8
__global__ __launch_bounds__(128) void combine_kernel(const float* __restrict__ ew,
                                                      const float* __restrict__ rw,
                                                      __half* __restrict__ wh,
                                                      int b0) {
    __shared__ float srw[B_ * E_];
    int tid = threadIdx.x;
    int oc = blockIdx.x * 2 + (tid >> 6);
    int icp = tid & 63;
    int bg = b0 + blockIdx.y * BGRP;
    srw[tid] = rw[tid];
    __syncthreads();

    float w[E_][2][9];
    #pragma unroll
    for (int e = 0; e < E_; e++) {
        const float* p = ew + (((size_t)e * COUT + oc) * CIN + 2 * icp) * 9;
        #pragma unroll
        for (int t = 0; t < 9; t++) { w[e][0][t] = p[t]; w[e][1][t] = p[9 + t]; }
    }

    #pragma unroll 1
    for (int bi = 0; bi < BGRP; bi++) {
        int b = bg + bi;
        float r0 = srw[b * 4 + 0], r1 = srw[b * 4 + 1];
        float r2 = srw[b * 4 + 2], r3 = srw[b * 4 + 3];
        __half* op = wh + ((size_t)b * COUT + oc) * RTAPS + 2 * icp;
        #pragma unroll
        for (int t = 0; t < 9; t++) {
            float v0 = w[0][0][t] * r0 + w[1][0][t] * r1 + w[2][0][t] * r2 + w[3][0][t] * r3;
            float v1 = w[0][1][t] * r0 + w[1][1][t] * r1 + w[2][1][t] * r2 + w[3][1][t] * r3;
            *(__half2*)(op + (size_t)t * 128) = __floats2half2_rn(v0, v1);
        }
    }
}

// ---------------------------------------------------------------------------
// 3) Implicit-GEMM conv via mma.sync (fp32 accum), half batch via b0.
//    (Structure byte-identical to the proven 147.6us R10 version.)
// ---------------------------------------------------------------------------
#define A_BYTES     16384
#define BB_BYTES    14336
#define STAGE_BYTES (A_BYTES + BB_BYTES)  // 30720
#define NSTAGE      3
#define SM_TOTAL    (NSTAGE * STAGE_BYTES)  // 92160

__device__ __forceinline__ void load_chunk(int c, uint32_t smb, int stage,
                                           const __half* __restrict__ wbase,
                                           const __half* __restrict__ xb,
                                           int oh0, int tid) {
    int t = c >> 1, h = c & 1;
    int dy = t / 3, dx = t - 3 * dy;
    uint32_t sa = smb + stage * STAGE_BYTES;
    uint32_t sb = sa + A_BYTES;

    const __half* wp = wbase + t * 128 + h * 64;
    #pragma unroll
    for (int rep = 0; rep < 4; rep++) {
        int idx = tid + rep * 256;
        int row = idx >> 3, seg = idx & 7;
        const char* src = (const char*)(wp + (size_t)row * RTAPS) + seg * 16;
        CPASYNC(sa + sw128((uint32_t)(idx * 16)), src, 16);
    }
    #pragma unroll
    for (int rep = 0; rep < 4; rep++) {
        int idx = tid + rep * 256;
        if (idx < 896) {
            int n = idx >> 3, seg = idx & 7;
            int p = (n >= 56) ? 1 : 0;
            int ow = n - 56 * p;
            int ih = 2 * (oh0 + p) - 1 + dy;
            int iw = 2 * ow - 1 + dx;
            bool ok = ((unsigned)ih < (unsigned)H_) && ((unsigned)iw < (unsigned)W_);
            const char* src = ok
                ? (const char*)(xb + ((size_t)ih * W_ + iw) * CIN + h * 64) + seg * 16
                : (const char*)xb;
            CPASYNC(sb + sw128((uint32_t)(idx * 16)), src, ok ? 16u : 0u);
        }
    }
}

__global__ __launch_bounds__(256, 2) void conv_mma_kernel(const __half* __restrict__ xh,
                                                          const __half* __restrict__ wgt,
                                                          float* __restrict__ out,
                                                          int b0) {
    extern __shared__ char sm[];
    uint32_t smb = smem_u32(sm);
    int tid = threadIdx.x, lane = tid & 31, wid = tid >> 5;
    int wm = wid & 3, wn = wid >> 2;
    int oh0 = blockIdx.x * 2;
    int ocb = blockIdx.y, b = b0 + blockIdx.z;

    const __half* wbase = wgt + ((size_t)b * COUT + ocb * 128) * RTAPS;
    const __half* xb = xh + (size_t)b * (H_ * W_) * CIN;

    float acc[2][7][4];
    #pragma unroll
    for (int mt = 0; mt < 2; mt++)
        #pragma unroll
        for (int nt = 0; nt < 7; nt++)
            #pragma unroll
            for (int q = 0; q < 4; q++) acc[mt][nt][q] = 0.f;

    load_chunk(0, smb, 0, wbase, xb, oh0, tid);
    CPCOMMIT();
    load_chunk(1, smb, 1, wbase, xb, oh0, tid);
    CPCOMMIT();

    int st = 0, st2 = 2;
    for (int c = 0; c < 18; c++) {
        if (c < 17) { CPWAIT1(); } else { CPWAIT0(); }
        __syncthreads();

        if (c + 2 < 18) {
            load_chunk(c + 2, smb, st2, wbase, xb, oh0, tid);
            CPCOMMIT();
        }

        uint32_t sa = smb + st * STAGE_BYTES;
        uint32_t sb = sa + A_BYTES;

        #pragma unroll
        for (int ks = 0; ks < 4; ks++) {
            int k0 = ks * 16;
            uint32_t afr[2][4];
            #pragma unroll
            for (int mt = 0; mt < 2; mt++) {
                int row = wm * 32 + mt * 16 + (lane & 15);
                int kk = k0 + ((lane >> 4) << 3);
                LDSM_X4(afr[mt][0], afr[mt][1], afr[mt][2], afr[mt][3],
                        sa + sw128((uint32_t)(row * 128 + kk * 2)));
            }
            uint32_t bfr[7][2];
            #pragma unroll
            for (int j = 0; j < 3; j++) {
                int n = wn * 56 + j * 16 + (lane & 7) + ((lane >> 4) << 3);
                int kk = k0 + (((lane >> 3) & 1) << 3);
                LDSM_X4(bfr[2 * j][0], bfr[2 * j][1], bfr[2 * j + 1][0], bfr[2 * j + 1][1],
                        sb + sw128((uint32_t)(n * 128 + kk * 2)));
            }
            {
                int n = wn * 56 + 48 + (lane & 7);
                int kk = k0 + (((lane >> 3) & 1) << 3);
                LDSM_X2(bfr[6][0], bfr[6][1],
                        sb + sw128((uint32_t)(n * 128 + kk * 2)));
            }
            #pragma unroll
            for (int mt = 0; mt < 2; mt++)
                #pragma unroll
                for (int nt = 0; nt < 7; nt++)
                    MMA16816(acc[mt][nt], afr[mt], bfr[nt][0], bfr[nt][1]);
        }

        st = (st == NSTAGE - 1) ? 0 : st + 1;
        st2 = (st2 == NSTAGE - 1) ? 0 : st2 + 1;
    }

    int r = lane >> 2;
    int cb = (lane & 3) * 2;
    int oh = oh0 + wn;
    #pragma unroll
    for (int mt = 0; mt < 2; mt++) {
        int oc = ocb * 128 + wm * 32 + mt * 16 + r;
        #pragma unroll
        for (int nt = 0; nt < 7; nt++) {
            int ow = nt * 8 + cb;
            float* op = out + (((size_t)b * COUT + oc) * HOUT + oh) * WOUT + ow;
            *(float2*)op = make_float2(acc[mt][nt][0], acc[mt][nt][1]);
            *(float2*)(op + (size_t)8 * HOUT * WOUT) =
                make_float2(acc[mt][nt][2], acc[mt][nt][3]);   // oc + 8
        }
    }
}

// ---------------------------------------------------------------------------
// Fork/join two half-batch chains on two streams so the DRAM-bound split_x of
// half 2 overlaps the tensor-bound conv of half 1.
// ---------------------------------------------------------------------------
extern "C" void kernel_launch(void* const* d_in, const int* in_sizes, int n_in,
                              void* d_out, int out_size) {
    const float* x    = (const float*)d_in[0];
    const float* rw_w = (const float*)d_in[1];
    const float* rw_b = (const float*)d_in[2];
    const float* ew   = (const float*)d_in[3];
    float* out = (float*)d_out;

    float *rw, *rowsum;
    __half *xh, *wh;
    cudaGetSymbolAddress((void**)&rw, g_rw);
    cudaGetSymbolAddress((void**)&rowsum, g_rowsum);
    cudaGetSymbolAddress((void**)&xh, g_xh);
    cudaGetSymbolAddress((void**)&wh, g_wh);

    static bool inited = false;
    static cudaStream_t s1;
    static cudaEvent_t eFork, eJoin;
    if (!inited) {
        cudaStreamCreateWithFlags(&s1, cudaStreamNonBlocking);
        cudaEventCreateWithFlags(&eFork, cudaEventDisableTiming);
        cudaEventCreateWithFlags(&eJoin, cudaEventDisableTiming);
        cudaFuncSetAttribute(split_x_kernel,
                             cudaFuncAttributeMaxDynamicSharedMemorySize, SPLIT_SMEM);
        cudaFuncSetAttribute(conv_mma_kernel,
                             cudaFuncAttributeMaxDynamicSharedMemorySize, SM_TOTAL);
        inited = true;
    }

    // --- half 1 split on the main (capture) stream ---
    split_x_kernel<<<HB * H_, 512, SPLIT_SMEM>>>(x, xh, rowsum, 0);

    // --- fork: s1 processes half 1's dependent chain ---
    cudaEventRecord(eFork, 0);
    cudaStreamWaitEvent(s1, eFork, 0);
    pool_route_kernel<<<HB, 128, 0, s1>>>(rowsum, rw_w, rw_b, rw, 0);
    combine_kernel<<<dim3(COUT / 2, HB / BGRP), 128, 0, s1>>>(ew, rw, wh, 0);
    conv_mma_kernel<<<dim3(HOUT / 2, 2, HB), 256, SM_TOTAL, s1>>>(xh, wh, out, 0);
    cudaEventRecord(eJoin, s1);

    // --- half 2 chain on the main stream (overlaps conv of half 1) ---
    split_x_kernel<<<HB * H_, 512, SPLIT_SMEM>>>(x, xh, rowsum, HB);
    pool_route_kernel<<<HB, 128>>>(rowsum, rw_w, rw_b, rw, HB);
    combine_kernel<<<dim3(COUT / 2, HB / BGRP), 128>>>(ew, rw, wh, HB);
    conv_mma_kernel<<<dim3(HOUT / 2, 2, HB), 256, SM_TOTAL>>>(xh, wh, out, HB);

    // --- join ---
    cudaStreamWaitEvent(0, eJoin, 0);
}